// round 1
// baseline (speedup 1.0000x reference)
#include <cuda_runtime.h>
#include <math.h>

#define B_    2048
#define S_    96
#define F_    32
#define H_    256
#define O_    6
#define LA_   32
#define WARM_ 96
#define STEPS_ 128
#define MB_   16
#define NTH_  256
#define NBLK_ (B_ / MB_)
#define HSTRIDE_ 18   // 16 data floats + 2 pad: 72B rows, 8B-aligned pairs, odd bank step

typedef unsigned long long ull;

// Static device scratch (no allocation allowed).
__device__ float4 g_WhhT[H_ * H_];   // [k][jh] -> (i,f,g,o) weights, k = 0..255
__device__ float4 g_WihT[F_ * H_];   // [k][jh] -> (i,f,g,o) weights, k = 0..31
__device__ float4 g_bias[H_];        // [jh]    -> (i,f,g,o) combined bias

// ---- packed fp32x2 helpers (sm_103a FFMA2 path) ----
__device__ __forceinline__ ull ffma2(ull a, ull b, ull c) {
    ull d;
    asm("fma.rn.f32x2 %0, %1, %2, %3;" : "=l"(d) : "l"(a), "l"(b), "l"(c));
    return d;
}
__device__ __forceinline__ ull splat2(float x) {
    ull d; unsigned u = __float_as_uint(x);
    asm("mov.b64 %0, {%1, %1};" : "=l"(d) : "r"(u));
    return d;
}
__device__ __forceinline__ float2 unpk(ull v) {
    unsigned lo, hi;
    asm("mov.b64 {%0, %1}, %2;" : "=r"(lo), "=r"(hi) : "l"(v));
    return make_float2(__uint_as_float(lo), __uint_as_float(hi));
}
__device__ __forceinline__ ull pk(float a, float b) {
    ull d;
    asm("mov.b64 %0, {%1, %2};" : "=l"(d) : "r"(__float_as_uint(a)), "r"(__float_as_uint(b)));
    return d;
}
__device__ __forceinline__ float sigf(float x) { return 1.0f / (1.0f + expf(-x)); }

// One-time (per launch) weight transpose/interleave + bias fold.
__global__ void pack_kernel(const float* __restrict__ Wih, const float* __restrict__ Whh,
                            const float* __restrict__ bih, const float* __restrict__ bhh) {
    int idx = blockIdx.x * blockDim.x + threadIdx.x;   // 65536 = 256k x 256jh
    int k  = idx >> 8;
    int jh = idx & 255;
    float4 v;
    v.x = Whh[(0 * H_ + jh) * H_ + k];
    v.y = Whh[(1 * H_ + jh) * H_ + k];
    v.z = Whh[(2 * H_ + jh) * H_ + k];
    v.w = Whh[(3 * H_ + jh) * H_ + k];
    g_WhhT[idx] = v;
    if (k < F_) {
        float4 u;
        u.x = Wih[(0 * H_ + jh) * F_ + k];
        u.y = Wih[(1 * H_ + jh) * F_ + k];
        u.z = Wih[(2 * H_ + jh) * F_ + k];
        u.w = Wih[(3 * H_ + jh) * F_ + k];
        g_WihT[k * H_ + jh] = u;
    }
    if (k == 0) {
        float4 b;
        b.x = bih[0 * H_ + jh] + bhh[0 * H_ + jh];
        b.y = bih[1 * H_ + jh] + bhh[1 * H_ + jh];
        b.z = bih[2 * H_ + jh] + bhh[2 * H_ + jh];
        b.w = bih[3 * H_ + jh] + bhh[3 * H_ + jh];
        g_bias[jh] = b;
    }
}

// GEMM fragment: accumulate KN k-slices from Wcol (stride H_ float4 per k) against
// the state matrix Sm ([k][r] rows, HSTRIDE_ floats per row). 2-deep LDG prefetch.
template <int KN>
__device__ __forceinline__ void gemm_part(const float4* __restrict__ Wcol,
                                          const float* __restrict__ Sm,
                                          ull (&acc)[4][8]) {
    float4 wa = Wcol[0];
    float4 wb = Wcol[H_];
#pragma unroll 1
    for (int k = 0; k < KN; k += 2) {
        float4 wn0 = Wcol[(((k + 2) & (KN - 1))) * H_];
        float4 wn1 = Wcol[(((k + 3) & (KN - 1))) * H_];
        {
            const ull* h2 = (const ull*)(Sm + k * HSTRIDE_);
            ull h[8];
#pragma unroll
            for (int p = 0; p < 8; p++) h[p] = h2[p];
            ull wi = splat2(wa.x), wf = splat2(wa.y), wg = splat2(wa.z), wo = splat2(wa.w);
#pragma unroll
            for (int p = 0; p < 8; p++) {
                acc[0][p] = ffma2(h[p], wi, acc[0][p]);
                acc[1][p] = ffma2(h[p], wf, acc[1][p]);
                acc[2][p] = ffma2(h[p], wg, acc[2][p]);
                acc[3][p] = ffma2(h[p], wo, acc[3][p]);
            }
        }
        {
            const ull* h2 = (const ull*)(Sm + (k + 1) * HSTRIDE_);
            ull h[8];
#pragma unroll
            for (int p = 0; p < 8; p++) h[p] = h2[p];
            ull wi = splat2(wb.x), wf = splat2(wb.y), wg = splat2(wb.z), wo = splat2(wb.w);
#pragma unroll
            for (int p = 0; p < 8; p++) {
                acc[0][p] = ffma2(h[p], wi, acc[0][p]);
                acc[1][p] = ffma2(h[p], wf, acc[1][p]);
                acc[2][p] = ffma2(h[p], wg, acc[2][p]);
                acc[3][p] = ffma2(h[p], wo, acc[3][p]);
            }
        }
        wa = wn0;
        wb = wn1;
    }
}

__global__ void __launch_bounds__(NTH_, 1)
lstm_kernel(const float* __restrict__ x, const float* __restrict__ Wfc,
            const float* __restrict__ bfc, float* __restrict__ out) {
    __shared__ __align__(16) float Hs[H_ * HSTRIDE_];  // [k=jh][r] h-state
    __shared__ __align__(16) float Xs[F_ * HSTRIDE_];  // [k=f][r]  staged x_t
    __shared__ float WfcS[O_ * H_];
    __shared__ float bfcS[O_];
    __shared__ float oS[MB_ * O_];

    const int tid = threadIdx.x;
    const int jh  = tid;                 // one hidden unit per thread
    const int b0  = blockIdx.x * MB_;

    for (int i = tid; i < H_ * HSTRIDE_; i += NTH_) Hs[i] = 0.0f;
    for (int i = tid; i < O_ * H_; i += NTH_) WfcS[i] = Wfc[i];
    if (tid < O_) bfcS[tid] = bfc[tid];

    float c[MB_];
#pragma unroll
    for (int r = 0; r < MB_; r++) c[r] = 0.0f;

    const float4 bias = g_bias[jh];
    const float4* WhhCol = g_WhhT + jh;
    const float4* WihCol = g_WihT + jh;

    __syncthreads();

    for (int t = 0; t < STEPS_; t++) {
        // ---- stage x_t (look-ahead steps replace features [0,6) with prev output) ----
        const int  ts = (t < WARM_) ? t : (t - WARM_);
        const bool la = (t >= WARM_);
#pragma unroll
        for (int i = 0; i < (MB_ * F_) / NTH_; i++) {
            int idx = tid + i * NTH_;
            int r = idx >> 5, f = idx & 31;
            float v;
            if (la && f < O_) v = oS[r * O_ + f];
            else              v = x[((size_t)(b0 + r) * S_ + ts) * F_ + f];
            Xs[f * HSTRIDE_ + r] = v;
        }
        __syncthreads();   // Xs ready; Hs stable

        // ---- gates = W_ih x_t + W_hh h + b  (packed over row pairs) ----
        ull acc[4][8];
        {
            ull bi = splat2(bias.x), bf = splat2(bias.y), bg = splat2(bias.z), bo = splat2(bias.w);
#pragma unroll
            for (int p = 0; p < 8; p++) {
                acc[0][p] = bi; acc[1][p] = bf; acc[2][p] = bg; acc[3][p] = bo;
            }
        }
        gemm_part<F_>(WihCol, Xs, acc);
        gemm_part<H_>(WhhCol, Hs, acc);

        // ---- elementwise LSTM cell (c in registers) ----
        float hn[MB_];
#pragma unroll
        for (int p = 0; p < 8; p++) {
            float2 gi = unpk(acc[0][p]);
            float2 gf = unpk(acc[1][p]);
            float2 gg = unpk(acc[2][p]);
            float2 go = unpk(acc[3][p]);
            float c0 = sigf(gf.x) * c[2 * p]     + sigf(gi.x) * tanhf(gg.x);
            float c1 = sigf(gf.y) * c[2 * p + 1] + sigf(gi.y) * tanhf(gg.y);
            c[2 * p]     = c0;
            c[2 * p + 1] = c1;
            hn[2 * p]     = sigf(go.x) * tanhf(c0);
            hn[2 * p + 1] = sigf(go.y) * tanhf(c1);
        }
        __syncthreads();   // everyone done reading old Hs
        {
            ull* hrow = (ull*)(Hs + jh * HSTRIDE_);
#pragma unroll
            for (int p = 0; p < 8; p++) hrow[p] = pk(hn[2 * p], hn[2 * p + 1]);
        }

        // ---- STE readout: out = (h>0) @ W_fc^T + b_fc  (steps 95..127) ----
        if (t >= WARM_ - 1) {
            __syncthreads();   // new Hs visible
            if (tid < MB_ * O_) {
                int r = tid & 15, oi = tid >> 4;
                float a = bfcS[oi];
                const float* wrow = &WfcS[oi * H_];
#pragma unroll 8
                for (int j2 = 0; j2 < H_; j2++)
                    a += (Hs[j2 * HSTRIDE_ + r] > 0.0f) ? wrow[j2] : 0.0f;
                oS[r * O_ + oi] = a;
                out[((size_t)(b0 + r) * (LA_ + 1) + (t - (WARM_ - 1))) * O_ + oi] = a;
            }
        }
        __syncthreads();   // Hs + oS ready for next step
    }
}

extern "C" void kernel_launch(void* const* d_in, const int* in_sizes, int n_in,
                              void* d_out, int out_size) {
    const float* x    = (const float*)d_in[0];
    const float* W_ih = (const float*)d_in[1];
    const float* W_hh = (const float*)d_in[2];
    const float* b_ih = (const float*)d_in[3];
    const float* b_hh = (const float*)d_in[4];
    const float* W_fc = (const float*)d_in[5];
    const float* b_fc = (const float*)d_in[6];
    float* out = (float*)d_out;

    pack_kernel<<<(H_ * H_) / 256, 256>>>(W_ih, W_hh, b_ih, b_hh);
    lstm_kernel<<<NBLK_, NTH_>>>(x, W_fc, b_fc, out);
}

// round 3
// speedup vs baseline: 1.2371x; 1.2371x over previous
#include <cuda_runtime.h>
#include <math.h>

#define B_     2048
#define S_     96
#define F_     32
#define H_     256
#define O_     6
#define LA_    32
#define WARM_  96
#define STEPS_ 128
#define MB_    14
#define PAIRS_ 7
#define NTH_   512
#define NBLK_  147        // ceil(2048 / 14)
#define HSTRIDE_ 18       // floats per state row (14 data + 4 pad), 8B-aligned pairs
#define KA_    112        // warpgroup A: Whh k in [0,112) (+ all 32 x-features)
#define KB_    144        // warpgroup B: Whh k in [112,256)

typedef unsigned long long ull;

// Static device scratch (no allocation allowed).
__device__ float4 g_WhhT[H_ * H_];   // [k][jh] -> (i,f,g,o)
__device__ float4 g_WihT[F_ * H_];   // [k][jh] -> (i,f,g,o)
__device__ float4 g_bias[H_];        // [jh]    -> combined bias

// ---- packed fp32x2 helpers ----
__device__ __forceinline__ ull ffma2(ull a, ull b, ull c) {
    ull d;
    asm("fma.rn.f32x2 %0, %1, %2, %3;" : "=l"(d) : "l"(a), "l"(b), "l"(c));
    return d;
}
__device__ __forceinline__ ull add2(ull a, ull b) {
    ull d;
    asm("add.rn.f32x2 %0, %1, %2;" : "=l"(d) : "l"(a), "l"(b));
    return d;
}
__device__ __forceinline__ ull splat2(float x) {
    ull d; unsigned u = __float_as_uint(x);
    asm("mov.b64 %0, {%1, %1};" : "=l"(d) : "r"(u));
    return d;
}
__device__ __forceinline__ float2 unpk(ull v) {
    unsigned lo, hi;
    asm("mov.b64 {%0, %1}, %2;" : "=r"(lo), "=r"(hi) : "l"(v));
    return make_float2(__uint_as_float(lo), __uint_as_float(hi));
}
__device__ __forceinline__ ull pk(float a, float b) {
    ull d;
    asm("mov.b64 %0, {%1, %2};" : "=l"(d) : "r"(__float_as_uint(a)), "r"(__float_as_uint(b)));
    return d;
}
// ACCURATE activations (R1-proven; fast-math variants blow past 1e-3 via STE chaos)
__device__ __forceinline__ float sigf(float x) { return 1.0f / (1.0f + expf(-x)); }

// One-time (per launch) weight transpose/interleave + bias fold.
__global__ void pack_kernel(const float* __restrict__ Wih, const float* __restrict__ Whh,
                            const float* __restrict__ bih, const float* __restrict__ bhh) {
    int idx = blockIdx.x * blockDim.x + threadIdx.x;
    int k  = idx >> 8;
    int jh = idx & 255;
    float4 v;
    v.x = Whh[(0 * H_ + jh) * H_ + k];
    v.y = Whh[(1 * H_ + jh) * H_ + k];
    v.z = Whh[(2 * H_ + jh) * H_ + k];
    v.w = Whh[(3 * H_ + jh) * H_ + k];
    g_WhhT[idx] = v;
    if (k < F_) {
        float4 u;
        u.x = Wih[(0 * H_ + jh) * F_ + k];
        u.y = Wih[(1 * H_ + jh) * F_ + k];
        u.z = Wih[(2 * H_ + jh) * F_ + k];
        u.w = Wih[(3 * H_ + jh) * F_ + k];
        g_WihT[k * H_ + jh] = u;
    }
    if (k == 0) {
        float4 b;
        b.x = bih[0 * H_ + jh] + bhh[0 * H_ + jh];
        b.y = bih[1 * H_ + jh] + bhh[1 * H_ + jh];
        b.z = bih[2 * H_ + jh] + bhh[2 * H_ + jh];
        b.w = bih[3 * H_ + jh] + bhh[3 * H_ + jh];
        g_bias[jh] = b;
    }
}

__device__ __forceinline__ void gemm_inner(const float* __restrict__ row, float4 w,
                                           ull (&acc)[4][PAIRS_]) {
    const ull* h2 = (const ull*)row;
    ull h[PAIRS_];
#pragma unroll
    for (int p = 0; p < PAIRS_; p++) h[p] = h2[p];
    ull wi = splat2(w.x), wf = splat2(w.y), wg = splat2(w.z), wo = splat2(w.w);
#pragma unroll
    for (int p = 0; p < PAIRS_; p++) {
        acc[0][p] = ffma2(h[p], wi, acc[0][p]);
        acc[1][p] = ffma2(h[p], wf, acc[1][p]);
        acc[2][p] = ffma2(h[p], wg, acc[2][p]);
        acc[3][p] = ffma2(h[p], wo, acc[3][p]);
    }
}

// KN even. Wcol stride = H_ float4 per k. Sm rows stride HSTRIDE_ floats.
template <int KN>
__device__ __forceinline__ void gemm_part(const float4* __restrict__ Wcol,
                                          const float* __restrict__ Sm,
                                          ull (&acc)[4][PAIRS_]) {
    float4 wa = Wcol[0];
    float4 wb = Wcol[H_];
#pragma unroll 1
    for (int k = 0; k < KN; k += 2) {
        int k2 = (k + 2 < KN) ? (k + 2) : 0;
        int k3 = (k + 3 < KN) ? (k + 3) : 1;
        float4 wn0 = Wcol[k2 * H_];
        float4 wn1 = Wcol[k3 * H_];
        gemm_inner(Sm + k * HSTRIDE_, wa, acc);
        gemm_inner(Sm + (k + 1) * HSTRIDE_, wb, acc);
        wa = wn0;
        wb = wn1;
    }
}

// Dynamic smem layout (floats):
//   Ex    [256][4][7] ull   : 14336 floats (57344 B)  -- partial-sum exchange / readout scratch
//   Hs    [256][18]         :  4608 floats
//   Xs    [32][18]          :   576 floats
//   WfcS  [6][256]          :  1536 floats
//   bfcS  [8]               :     8 floats
//   oS    [14*6]            :    84 floats
#define SM_EX_   0
#define SM_HS_   14336
#define SM_XS_   (SM_HS_ + H_ * HSTRIDE_)
#define SM_WFC_  (SM_XS_ + F_ * HSTRIDE_)
#define SM_BFC_  (SM_WFC_ + O_ * H_)
#define SM_OS_   (SM_BFC_ + 8)
#define SM_TOTF_ (SM_OS_ + MB_ * O_ + 4)
#define SMEM_BYTES_ (SM_TOTF_ * 4)

__global__ void __launch_bounds__(NTH_, 1)
lstm_kernel(const float* __restrict__ x, const float* __restrict__ Wfc,
            const float* __restrict__ bfc, float* __restrict__ out) {
    extern __shared__ __align__(16) float smem[];
    ull*   Ex   = (ull*)(smem + SM_EX_);     // flat [jh][g][p]
    float* Hs   = smem + SM_HS_;
    float* Xs   = smem + SM_XS_;
    float* WfcS = smem + SM_WFC_;
    float* bfcS = smem + SM_BFC_;
    float* oS   = smem + SM_OS_;

    const int tid = threadIdx.x;
    const int jh  = tid & 255;
    const int wg  = tid >> 8;        // 0 = A, 1 = B
    const int b0  = blockIdx.x * MB_;

    for (int i = tid; i < H_ * HSTRIDE_; i += NTH_) Hs[i] = 0.0f;
    for (int i = tid; i < O_ * H_; i += NTH_) WfcS[i] = Wfc[i];
    if (tid < O_) bfcS[tid] = bfc[tid];

    float c[8];
#pragma unroll
    for (int r = 0; r < 8; r++) c[r] = 0.0f;

    const int pbase = wg ? 4 : 0;    // elementwise pair range per warpgroup
    const int np    = wg ? 3 : 4;

    const float4 bias = g_bias[jh];  // used by A only

    // ---- x stager state: thread slots (f, pair), 224 slots ----
    const bool stager = tid < F_ * PAIRS_;
    int xf = 0, xp = 0;
    const float* xr0 = x;
    const float* xr1 = x;
    float xa = 0.0f, xb = 0.0f;
    if (stager) {
        xf = tid / PAIRS_;
        xp = tid - xf * PAIRS_;
        int r0 = b0 + 2 * xp;     if (r0 > B_ - 1) r0 = B_ - 1;
        int r1 = b0 + 2 * xp + 1; if (r1 > B_ - 1) r1 = B_ - 1;
        xr0 = x + (size_t)r0 * S_ * F_ + xf;
        xr1 = x + (size_t)r1 * S_ * F_ + xf;
        xa = xr0[0];              // t = 0 prefetch
        xb = xr1[0];
    }

    __syncthreads();

    for (int t = 0; t < STEPS_; t++) {
        const bool la = (t >= WARM_);

        // ---- stage Xs (prefetched x; look-ahead overrides f<6 with prev output) ----
        if (stager) {
            float v0 = xa, v1 = xb;
            if (la && xf < O_) {
                v0 = oS[(2 * xp) * O_ + xf];
                v1 = oS[(2 * xp + 1) * O_ + xf];
            }
            *(ull*)(Xs + xf * HSTRIDE_ + 2 * xp) = pk(v0, v1);
            int tn = t + 1;
            if (tn < STEPS_) {
                int tsn = (tn < WARM_) ? tn : (tn - WARM_);
                xa = xr0[(size_t)tsn * F_];
                xb = xr1[(size_t)tsn * F_];
            }
        }
        __syncthreads();   // Xs ready

        // ---- split-k gates GEMM ----
        ull acc[4][PAIRS_];
        if (wg == 0) {
            ull bi = splat2(bias.x), bf = splat2(bias.y),
                bg = splat2(bias.z), bo = splat2(bias.w);
#pragma unroll
            for (int p = 0; p < PAIRS_; p++) {
                acc[0][p] = bi; acc[1][p] = bf; acc[2][p] = bg; acc[3][p] = bo;
            }
            gemm_part<F_>(g_WihT + jh, Xs, acc);
            gemm_part<KA_>(g_WhhT + jh, Hs, acc);
        } else {
            ull z = splat2(0.0f);
#pragma unroll
            for (int p = 0; p < PAIRS_; p++) {
                acc[0][p] = z; acc[1][p] = z; acc[2][p] = z; acc[3][p] = z;
            }
            gemm_part<KB_>(g_WhhT + (size_t)KA_ * H_ + jh, Hs + KA_ * HSTRIDE_, acc);
        }

        // ---- exchange complement partials ----
        {
            ull* eb = Ex + (size_t)jh * 28;
            if (wg == 0) {
#pragma unroll
                for (int g = 0; g < 4; g++)
#pragma unroll
                    for (int p = 4; p < 7; p++) eb[g * 7 + p] = acc[g][p];
            } else {
#pragma unroll
                for (int g = 0; g < 4; g++)
#pragma unroll
                    for (int p = 0; p < 4; p++) eb[g * 7 + p] = acc[g][p];
            }
        }
        __syncthreads();   // partials visible; all Hs reads complete

        // ---- reduce own pairs + elementwise cell + write new h ----
        {
            const ull* eb = Ex + (size_t)jh * 28;
#pragma unroll
            for (int q = 0; q < 4; q++) {
                if (q >= np) break;
                int p = pbase + q;
                ull gi2 = add2(acc[0][p], eb[0 * 7 + p]);
                ull gf2 = add2(acc[1][p], eb[1 * 7 + p]);
                ull gg2 = add2(acc[2][p], eb[2 * 7 + p]);
                ull go2 = add2(acc[3][p], eb[3 * 7 + p]);
                float2 gi = unpk(gi2), gf = unpk(gf2), gg = unpk(gg2), go = unpk(go2);
                float c0 = sigf(gf.x) * c[2 * q]     + sigf(gi.x) * tanhf(gg.x);
                float c1 = sigf(gf.y) * c[2 * q + 1] + sigf(gi.y) * tanhf(gg.y);
                c[2 * q]     = c0;
                c[2 * q + 1] = c1;
                float h0 = sigf(go.x) * tanhf(c0);
                float h1 = sigf(go.y) * tanhf(c1);
                *(ull*)(Hs + jh * HSTRIDE_ + 2 * p) = pk(h0, h1);
            }
        }
        __syncthreads();   // new Hs complete

        // ---- STE readout: out = (h>0) @ W_fc^T + b_fc  (t = 95..127) ----
        if (t >= WARM_ - 1) {
            float* red = (float*)Ex;   // scratch: [84][4]
            if (tid < MB_ * O_ * 4) {
                int slot  = tid >> 2;        // (r, oi)
                int chunk = tid & 3;
                int r  = slot / O_;
                int oi = slot - r * O_;
                const float* wrow = WfcS + oi * H_;
                float a0 = 0.0f, a1 = 0.0f;
                int jb = chunk * 64;
#pragma unroll 8
                for (int j = 0; j < 64; j += 2) {
                    a0 += (Hs[(jb + j) * HSTRIDE_ + r] > 0.0f)     ? wrow[jb + j]     : 0.0f;
                    a1 += (Hs[(jb + j + 1) * HSTRIDE_ + r] > 0.0f) ? wrow[jb + j + 1] : 0.0f;
                }
                red[slot * 4 + chunk] = a0 + a1;
            }
            __syncthreads();
            if (tid < MB_ * O_) {
                int r  = tid / O_;
                int oi = tid - r * O_;
                float a = bfcS[oi] + red[tid * 4 + 0] + red[tid * 4 + 1]
                                   + red[tid * 4 + 2] + red[tid * 4 + 3];
                oS[tid] = a;
                if (b0 + r < B_)
                    out[((size_t)(b0 + r) * (LA_ + 1) + (t - (WARM_ - 1))) * O_ + oi] = a;
            }
            __syncthreads();   // oS ready for next step's stager
        }
    }
}

extern "C" void kernel_launch(void* const* d_in, const int* in_sizes, int n_in,
                              void* d_out, int out_size) {
    const float* x    = (const float*)d_in[0];
    const float* W_ih = (const float*)d_in[1];
    const float* W_hh = (const float*)d_in[2];
    const float* b_ih = (const float*)d_in[3];
    const float* b_hh = (const float*)d_in[4];
    const float* W_fc = (const float*)d_in[5];
    const float* b_fc = (const float*)d_in[6];
    float* out = (float*)d_out;

    cudaFuncSetAttribute(lstm_kernel, cudaFuncAttributeMaxDynamicSharedMemorySize,
                         SMEM_BYTES_);

    pack_kernel<<<(H_ * H_) / 256, 256>>>(W_ih, W_hh, b_ih, b_hh);
    lstm_kernel<<<NBLK_, NTH_, SMEM_BYTES_>>>(x, W_fc, b_fc, out);
}

// round 4
// speedup vs baseline: 1.2470x; 1.0080x over previous
#include <cuda_runtime.h>
#include <math.h>

#define B_     2048
#define S_     96
#define F_     32
#define H_     256
#define O_     6
#define LA_    32
#define WARM_  96
#define STEPS_ 128
#define MB_    14
#define PAIRS_ 7
#define NTH_   512
#define NBLK_  147        // ceil(2048 / 14)
#define KTOT_  (F_ + H_)  // 288 combined k range (x features then h)
#define KPAD_  296        // +8 pad rows so linear prefetch never goes OOB
#define HSTRIDE_ 20       // floats per state row: 14 data + 6 pad, 16B-aligned rows

typedef unsigned long long ull;

// Static device scratch (no allocation allowed).
// Gate-split weight layout: [k][jh] -> float2 of the two gates this WG owns.
__device__ float2 g_Wif[KPAD_ * H_];   // gates (i, f)
__device__ float2 g_Wgo[KPAD_ * H_];   // gates (g, o)
__device__ float4 g_bias[H_];          // combined bias (i,f,g,o)

// ---- packed fp32x2 helpers ----
__device__ __forceinline__ ull ffma2(ull a, ull b, ull c) {
    ull d;
    asm("fma.rn.f32x2 %0, %1, %2, %3;" : "=l"(d) : "l"(a), "l"(b), "l"(c));
    return d;
}
__device__ __forceinline__ ull splat2(float x) {
    ull d; unsigned u = __float_as_uint(x);
    asm("mov.b64 %0, {%1, %1};" : "=l"(d) : "r"(u));
    return d;
}
__device__ __forceinline__ float2 unpk(ull v) {
    unsigned lo, hi;
    asm("mov.b64 {%0, %1}, %2;" : "=r"(lo), "=r"(hi) : "l"(v));
    return make_float2(__uint_as_float(lo), __uint_as_float(hi));
}
__device__ __forceinline__ ull pk(float a, float b) {
    ull d;
    asm("mov.b64 %0, {%1, %2};" : "=l"(d) : "r"(__float_as_uint(a)), "r"(__float_as_uint(b)));
    return d;
}
// ACCURATE activations (fast-math variants fail: STE chaos amplifies ~1e-5 -> 2.4e-3)
__device__ __forceinline__ float sigf(float x) { return 1.0f / (1.0f + expf(-x)); }

// One-time weight interleave: combined (x|h) k range, gate-pair split, bias fold.
__global__ void pack_kernel(const float* __restrict__ Wih, const float* __restrict__ Whh,
                            const float* __restrict__ bih, const float* __restrict__ bhh) {
    int idx = blockIdx.x * blockDim.x + threadIdx.x;   // KPAD_*256 threads
    if (idx >= KPAD_ * H_) return;
    int k  = idx >> 8;
    int jh = idx & 255;
    float wi = 0.f, wf = 0.f, wg = 0.f, wo = 0.f;
    if (k < F_) {
        wi = Wih[(0 * H_ + jh) * F_ + k];
        wf = Wih[(1 * H_ + jh) * F_ + k];
        wg = Wih[(2 * H_ + jh) * F_ + k];
        wo = Wih[(3 * H_ + jh) * F_ + k];
    } else if (k < KTOT_) {
        int kk = k - F_;
        wi = Whh[(0 * H_ + jh) * H_ + kk];
        wf = Whh[(1 * H_ + jh) * H_ + kk];
        wg = Whh[(2 * H_ + jh) * H_ + kk];
        wo = Whh[(3 * H_ + jh) * H_ + kk];
    }
    g_Wif[idx] = make_float2(wi, wf);
    g_Wgo[idx] = make_float2(wg, wo);
    if (k == 0) {
        float4 b;
        b.x = bih[0 * H_ + jh] + bhh[0 * H_ + jh];
        b.y = bih[1 * H_ + jh] + bhh[1 * H_ + jh];
        b.z = bih[2 * H_ + jh] + bhh[2 * H_ + jh];
        b.w = bih[3 * H_ + jh] + bhh[3 * H_ + jh];
        g_bias[jh] = b;
    }
}

// One k-slice: 14 batch elements (7 pairs) x 2 gates.
__device__ __forceinline__ void gemm_body(const float* __restrict__ row, float2 w,
                                          ull (&a0)[PAIRS_], ull (&a1)[PAIRS_]) {
    ulonglong2 p0 = *(const ulonglong2*)(row);
    ulonglong2 p1 = *(const ulonglong2*)(row + 4);
    ulonglong2 p2 = *(const ulonglong2*)(row + 8);
    ull h6 = *(const ull*)(row + 12);
    ull w0 = splat2(w.x), w1 = splat2(w.y);
    a0[0] = ffma2(p0.x, w0, a0[0]);  a1[0] = ffma2(p0.x, w1, a1[0]);
    a0[1] = ffma2(p0.y, w0, a0[1]);  a1[1] = ffma2(p0.y, w1, a1[1]);
    a0[2] = ffma2(p1.x, w0, a0[2]);  a1[2] = ffma2(p1.x, w1, a1[2]);
    a0[3] = ffma2(p1.y, w0, a0[3]);  a1[3] = ffma2(p1.y, w1, a1[3]);
    a0[4] = ffma2(p2.x, w0, a0[4]);  a1[4] = ffma2(p2.x, w1, a1[4]);
    a0[5] = ffma2(p2.y, w0, a0[5]);  a1[5] = ffma2(p2.y, w1, a1[5]);
    a0[6] = ffma2(h6,   w0, a0[6]);  a1[6] = ffma2(h6,   w1, a1[6]);
}

// Dynamic smem layout (floats):
//   S     [288][20]       : 5760 floats   (rows 0..31 = x_t, rows 32..287 = h)
//   Ex    [256][16] ull   : 8192 floats   (gate exchange / readout scratch)
//   WfcS  [6][256]        : 1536
//   bfcS  [8], oS [84+pad]
#define SM_S_    0
#define SM_EX_   (SM_S_ + KTOT_ * HSTRIDE_)
#define SM_WFC_  (SM_EX_ + 256 * 16 * 2)
#define SM_BFC_  (SM_WFC_ + O_ * H_)
#define SM_OS_   (SM_BFC_ + 8)
#define SM_TOTF_ (SM_OS_ + MB_ * O_ + 4)
#define SMEM_BYTES_ (SM_TOTF_ * 4)

__global__ void __launch_bounds__(NTH_, 1)
lstm_kernel(const float* __restrict__ x, const float* __restrict__ Wfc,
            const float* __restrict__ bfc, float* __restrict__ out) {
    extern __shared__ __align__(16) float smem[];
    float* S    = smem + SM_S_;
    ull*   Ex   = (ull*)(smem + SM_EX_);     // [jh][16]
    float* WfcS = smem + SM_WFC_;
    float* bfcS = smem + SM_BFC_;
    float* oS   = smem + SM_OS_;

    const int tid = threadIdx.x;
    const int jh  = tid & 255;
    const int wg  = tid >> 8;        // 0: gates (i,f),  1: gates (g,o)
    const int b0  = blockIdx.x * MB_;

    for (int i = tid; i < KTOT_ * HSTRIDE_; i += NTH_) S[i] = 0.0f;
    for (int i = tid; i < O_ * H_; i += NTH_) WfcS[i] = Wfc[i];
    if (tid < O_) bfcS[tid] = bfc[tid];

    // c state: WG-A owns rows 0..7 (pairs 0..3); WG-B owns rows 8..13 (pairs 4..6)
    float c[8];
#pragma unroll
    for (int r = 0; r < 8; r++) c[r] = 0.0f;

    const float4 bias = g_bias[jh];
    const float2* __restrict__ Wcol = (wg == 0 ? g_Wif : g_Wgo) + jh;
    const float  bg0 = wg == 0 ? bias.x : bias.z;
    const float  bg1 = wg == 0 ? bias.y : bias.w;

    float* Hrow = S + (F_ + jh) * HSTRIDE_;
    ull*   ExRow = Ex + (size_t)jh * 16;

    // ---- x stager: thread slots (f, pair), 224 slots ----
    const bool stager = tid < F_ * PAIRS_;
    int xf = 0, xp = 0;
    const float* xr0 = x;
    const float* xr1 = x;
    float xa = 0.0f, xb = 0.0f;
    if (stager) {
        xf = tid / PAIRS_;
        xp = tid - xf * PAIRS_;
        int r0 = b0 + 2 * xp;     if (r0 > B_ - 1) r0 = B_ - 1;
        int r1 = b0 + 2 * xp + 1; if (r1 > B_ - 1) r1 = B_ - 1;
        xr0 = x + (size_t)r0 * S_ * F_ + xf;
        xr1 = x + (size_t)r1 * S_ * F_ + xf;
        xa = xr0[0];
        xb = xr1[0];
    }

    __syncthreads();

    for (int t = 0; t < STEPS_; t++) {
        const bool la = (t >= WARM_);

        // ---- stage x_t into S rows 0..31 (la steps override f<6 with prev output) ----
        if (stager) {
            float v0 = xa, v1 = xb;
            if (la && xf < O_) {
                v0 = oS[(2 * xp) * O_ + xf];
                v1 = oS[(2 * xp + 1) * O_ + xf];
            }
            *(ull*)(S + xf * HSTRIDE_ + 2 * xp) = pk(v0, v1);
            int tn = t + 1;
            if (tn < STEPS_) {
                int tsn = (tn < WARM_) ? tn : (tn - WARM_);
                xa = xr0[(size_t)tsn * F_];
                xb = xr1[(size_t)tsn * F_];
            }
        }
        __syncthreads();   // S (x rows) ready; h rows stable from prev step

        // ---- gate-pair GEMM over combined k = 0..287 ----
        ull a0[PAIRS_], a1[PAIRS_];
        {
            ull b0v = splat2(bg0), b1v = splat2(bg1);
#pragma unroll
            for (int p = 0; p < PAIRS_; p++) { a0[p] = b0v; a1[p] = b1v; }
        }
        {
            float2 w0 = Wcol[0 * H_], w1 = Wcol[1 * H_],
                   w2 = Wcol[2 * H_], w3 = Wcol[3 * H_];
            const float2* Wq = Wcol + 4 * H_;
            const float*  Sr = S;
#pragma unroll 1
            for (int k = 0; k < KTOT_; k += 4) {
                float2 n0 = Wq[0 * H_], n1 = Wq[1 * H_],
                       n2 = Wq[2 * H_], n3 = Wq[3 * H_];
                gemm_body(Sr + 0 * HSTRIDE_, w0, a0, a1);
                gemm_body(Sr + 1 * HSTRIDE_, w1, a0, a1);
                gemm_body(Sr + 2 * HSTRIDE_, w2, a0, a1);
                gemm_body(Sr + 3 * HSTRIDE_, w3, a0, a1);
                w0 = n0; w1 = n1; w2 = n2; w3 = n3;
                Wq += 4 * H_;
                Sr += 4 * HSTRIDE_;
            }
        }

        // ---- exchange complement gate partials ----
        if (wg == 0) {            // A gives (i,f) for pairs 4..6  -> slots 0..5
#pragma unroll
            for (int q = 0; q < 3; q++) {
                ExRow[2 * q]     = a0[4 + q];
                ExRow[2 * q + 1] = a1[4 + q];
            }
        } else {                  // B gives (g,o) for pairs 0..3  -> slots 6..13
#pragma unroll
            for (int q = 0; q < 4; q++) {
                ExRow[6 + 2 * q] = a0[q];
                ExRow[7 + 2 * q] = a1[q];
            }
        }
        __syncthreads();   // partials visible; all S reads complete

        // ---- elementwise LSTM cell + write new h ----
        if (wg == 0) {
#pragma unroll
            for (int q = 0; q < 4; q++) {
                float2 gi = unpk(a0[q]);
                float2 gf = unpk(a1[q]);
                float2 gg = unpk(ExRow[6 + 2 * q]);
                float2 go = unpk(ExRow[7 + 2 * q]);
                float c0 = sigf(gf.x) * c[2 * q]     + sigf(gi.x) * tanhf(gg.x);
                float c1 = sigf(gf.y) * c[2 * q + 1] + sigf(gi.y) * tanhf(gg.y);
                c[2 * q] = c0; c[2 * q + 1] = c1;
                *(ull*)(Hrow + 2 * q) = pk(sigf(go.x) * tanhf(c0),
                                           sigf(go.y) * tanhf(c1));
            }
        } else {
#pragma unroll
            for (int q = 0; q < 3; q++) {
                int p = 4 + q;
                float2 gi = unpk(ExRow[2 * q]);
                float2 gf = unpk(ExRow[2 * q + 1]);
                float2 gg = unpk(a0[p]);
                float2 go = unpk(a1[p]);
                float c0 = sigf(gf.x) * c[2 * q]     + sigf(gi.x) * tanhf(gg.x);
                float c1 = sigf(gf.y) * c[2 * q + 1] + sigf(gi.y) * tanhf(gg.y);
                c[2 * q] = c0; c[2 * q + 1] = c1;
                *(ull*)(Hrow + 2 * p) = pk(sigf(go.x) * tanhf(c0),
                                           sigf(go.y) * tanhf(c1));
            }
        }
        __syncthreads();   // new h complete

        // ---- STE readout: out = (h>0) @ W_fc^T + b_fc  (t = 95..127) ----
        if (t >= WARM_ - 1) {
            float* red = (float*)Ex;   // scratch [84][4] (Ex dead until next exchange)
            const float* Hs = S + F_ * HSTRIDE_;
            if (tid < MB_ * O_ * 4) {
                int slot  = tid >> 2;
                int chunk = tid & 3;
                int r  = slot / O_;
                int oi = slot - r * O_;
                const float* wrow = WfcS + oi * H_;
                float s0 = 0.0f, s1 = 0.0f;
                int jb = chunk * 64;
#pragma unroll 8
                for (int j = 0; j < 64; j += 2) {
                    s0 += (Hs[(jb + j) * HSTRIDE_ + r] > 0.0f)     ? wrow[jb + j]     : 0.0f;
                    s1 += (Hs[(jb + j + 1) * HSTRIDE_ + r] > 0.0f) ? wrow[jb + j + 1] : 0.0f;
                }
                red[slot * 4 + chunk] = s0 + s1;
            }
            __syncthreads();
            if (tid < MB_ * O_) {
                int r  = tid / O_;
                int oi = tid - r * O_;
                float a = bfcS[oi] + red[tid * 4 + 0] + red[tid * 4 + 1]
                                   + red[tid * 4 + 2] + red[tid * 4 + 3];
                oS[tid] = a;
                if (b0 + r < B_)
                    out[((size_t)(b0 + r) * (LA_ + 1) + (t - (WARM_ - 1))) * O_ + oi] = a;
            }
            __syncthreads();   // oS ready; red scratch dead before next exchange
        }
    }
}

extern "C" void kernel_launch(void* const* d_in, const int* in_sizes, int n_in,
                              void* d_out, int out_size) {
    const float* x    = (const float*)d_in[0];
    const float* W_ih = (const float*)d_in[1];
    const float* W_hh = (const float*)d_in[2];
    const float* b_ih = (const float*)d_in[3];
    const float* b_hh = (const float*)d_in[4];
    const float* W_fc = (const float*)d_in[5];
    const float* b_fc = (const float*)d_in[6];
    float* out = (float*)d_out;

    cudaFuncSetAttribute(lstm_kernel, cudaFuncAttributeMaxDynamicSharedMemorySize,
                         SMEM_BYTES_);

    pack_kernel<<<(KPAD_ * H_ + 255) / 256, 256>>>(W_ih, W_hh, b_ih, b_hh);
    lstm_kernel<<<NBLK_, NTH_, SMEM_BYTES_>>>(x, W_fc, b_fc, out);
}